// round 2
// baseline (speedup 1.0000x reference)
#include <cuda_runtime.h>
#include <cuda_bf16.h>
#include <math.h>

// ---------------- problem constants ----------------
constexpr int T    = 4096;   // tokens (B*C)
constexpr int E    = 8;      // experts
constexpr int CAPC = 1280;   // capacity per expert
constexpr int D    = 1024;   // model dim
constexpr int F    = 4096;   // hidden dim (4*d)

// ---------------- scratch (device globals; no allocation allowed) ----------------
__device__ int   d_e0[T];
__device__ int   d_e1[T];
__device__ float d_w0[T];
__device__ float d_w1[T];
__device__ int   d_slot0[T];
__device__ int   d_slot1[T];
__device__ int   d_disp_tok[E * CAPC];
__device__ int   d_count[E];

__device__ float d_xe[(size_t)E * CAPC * D];   // dispatched tokens   [E,cap,D]  ~42MB
__device__ float d_h [(size_t)E * CAPC * F];   // hidden activations  [E,cap,F]  ~168MB
__device__ float d_eo[(size_t)E * CAPC * D];   // expert outputs      [E,cap,D]  ~42MB

__device__ __forceinline__ float gelu_exact(float v) {
    return 0.5f * v * (1.0f + erff(v * 0.70710678118654752f));
}

// ---------------- 1. router: logits -> top2 + softmax weights ----------------
__global__ void router_kernel(const float* __restrict__ x, const float* __restrict__ wg) {
    __shared__ float s_wg[E * D];          // [e][i] layout, 32KB
    int tid = threadIdx.x;
    for (int idx = tid; idx < E * D; idx += blockDim.x) {
        int i = idx / E, e = idx % E;      // wg is [D, E] row-major
        s_wg[e * D + i] = wg[idx];
    }
    __syncthreads();

    int lane = tid & 31, wid = tid >> 5;
    int t = blockIdx.x * (blockDim.x >> 5) + wid;
    const float* xr = x + (size_t)t * D;

    float acc[E];
#pragma unroll
    for (int e = 0; e < E; e++) acc[e] = 0.f;

    for (int i = lane; i < D; i += 32) {
        float xv = xr[i];
#pragma unroll
        for (int e = 0; e < E; e++) acc[e] = fmaf(xv, s_wg[e * D + i], acc[e]);
    }
#pragma unroll
    for (int e = 0; e < E; e++) {
#pragma unroll
        for (int o = 16; o > 0; o >>= 1)
            acc[e] += __shfl_down_sync(0xffffffffu, acc[e], o);
    }
    if (lane == 0) {
        int e0 = 0; float v0 = acc[0];
        for (int e = 1; e < E; e++) if (acc[e] > v0) { v0 = acc[e]; e0 = e; }
        int e1 = -1; float v1 = -INFINITY;
        for (int e = 0; e < E; e++) if (e != e0 && acc[e] > v1) { v1 = acc[e]; e1 = e; }
        float ex = expf(v1 - v0);              // stable softmax over the two kept logits
        float denom = 1.0f + ex;
        d_e0[t] = e0; d_e1[t] = e1;
        d_w0[t] = 1.0f / denom;
        d_w1[t] = ex / denom;
    }
}

// ---------------- 2. capacity rank: per-expert prefix over (k-major, t-major) order ----------------
__global__ void rank_kernel() {
    int e = blockIdx.x;                    // one block per expert
    int tid = threadIdx.x, lane = tid & 31, wid = tid >> 5;
    __shared__ int wsum[32];
    int offset = 0;
    for (int k = 0; k < 2; k++) {
        const int* top = (k == 0) ? d_e0 : d_e1;
        int* slotArr   = (k == 0) ? d_slot0 : d_slot1;
        for (int base = 0; base < T; base += 1024) {
            int t = base + tid;
            int flag = (top[t] == e) ? 1 : 0;
            unsigned bal = __ballot_sync(0xffffffffu, flag);
            int myPre = __popc(bal & ((1u << lane) - 1u));
            if (lane == 0) wsum[wid] = __popc(bal);
            __syncthreads();
            int wbase = 0, tileTot = 0;
            for (int w = 0; w < 32; w++) {
                int s = wsum[w];
                if (w < wid) wbase += s;
                tileTot += s;
            }
            if (flag) {
                int r = offset + wbase + myPre;
                if (r < CAPC) {
                    slotArr[t] = r;
                    d_disp_tok[e * CAPC + r] = t;
                } else {
                    slotArr[t] = -1;       // dropped by capacity
                }
            }
            offset += tileTot;
            __syncthreads();
        }
    }
    if (tid == 0) d_count[e] = offset < CAPC ? offset : CAPC;
}

// ---------------- 3. gather tokens into per-expert batches ----------------
__global__ void gather_kernel(const float* __restrict__ x) {
    int idx = blockIdx.x;                  // e*CAPC + slot
    int e = idx / CAPC, s = idx % CAPC;
    if (s >= d_count[e]) return;           // unfilled slots are never read downstream
    int t = d_disp_tok[idx];
    int j = threadIdx.x * 4;               // 256 threads * float4 = 1024 floats
    *(float4*)&d_xe[(size_t)idx * D + j] = *(const float4*)&x[(size_t)t * D + j];
}

// ---------------- 4. batched tiled SGEMM (optionally fused exact-GELU) ----------------
template <bool DO_GELU>
__global__ __launch_bounds__(256) void sgemm_kernel(
    const float* __restrict__ A, const float* __restrict__ B, float* __restrict__ C,
    int M, int N, int K, size_t sA, size_t sB, size_t sC)
{
    constexpr int BM = 128, BN = 128, BK = 8, TM = 8, TN = 8;
    const int ez = blockIdx.z;
    A += (size_t)ez * sA;
    B += (size_t)ez * sB;
    C += (size_t)ez * sC;

    __shared__ float As[BK][BM];
    __shared__ float Bs[BK][BN];

    const int tid  = threadIdx.x;
    const int brow = blockIdx.y, bcol = blockIdx.x;
    const float* Ab = A + (size_t)brow * BM * K;
    const float* Bb = B + (size_t)bcol * BN;

    const int aRow = tid >> 1;             // 128 rows, 2 threads/row
    const int aCol = (tid & 1) * 4;
    const int bRow = tid >> 5;             // 8 rows, 32 threads/row
    const int bCol = (tid & 31) * 4;
    const int tr = tid >> 4, tc = tid & 15;

    float acc[TM][TN] = {};

    for (int k0 = 0; k0 < K; k0 += BK) {
        float4 av = *(const float4*)(Ab + (size_t)aRow * K + k0 + aCol);
        As[aCol + 0][aRow] = av.x;
        As[aCol + 1][aRow] = av.y;
        As[aCol + 2][aRow] = av.z;
        As[aCol + 3][aRow] = av.w;
        *(float4*)(&Bs[bRow][bCol]) = *(const float4*)(Bb + (size_t)(k0 + bRow) * N + bCol);
        __syncthreads();

#pragma unroll
        for (int kk = 0; kk < BK; kk++) {
            float ra[TM], rb[TN];
#pragma unroll
            for (int i = 0; i < TM; i++) ra[i] = As[kk][tr * TM + i];
#pragma unroll
            for (int j = 0; j < TN; j++) rb[j] = Bs[kk][tc * TN + j];
#pragma unroll
            for (int i = 0; i < TM; i++)
#pragma unroll
                for (int j = 0; j < TN; j++)
                    acc[i][j] = fmaf(ra[i], rb[j], acc[i][j]);
        }
        __syncthreads();
    }

#pragma unroll
    for (int i = 0; i < TM; i++) {
        size_t row = (size_t)(brow * BM + tr * TM + i);
        float* Crow = C + row * N + bcol * BN + tc * TN;
#pragma unroll
        for (int j = 0; j < TN; j += 4) {
            float4 v;
            v.x = DO_GELU ? gelu_exact(acc[i][j + 0]) : acc[i][j + 0];
            v.y = DO_GELU ? gelu_exact(acc[i][j + 1]) : acc[i][j + 1];
            v.z = DO_GELU ? gelu_exact(acc[i][j + 2]) : acc[i][j + 2];
            v.w = DO_GELU ? gelu_exact(acc[i][j + 3]) : acc[i][j + 3];
            *(float4*)(Crow + j) = v;
        }
    }
}

// ---------------- 5. weighted combine ----------------
__global__ void combine_kernel(float* __restrict__ out) {
    int t = blockIdx.x;
    int j = threadIdx.x * 4;
    float4 r = {0.f, 0.f, 0.f, 0.f};
    int s0 = d_slot0[t];
    if (s0 >= 0) {
        float w = d_w0[t];
        const float4 v = *(const float4*)&d_eo[((size_t)d_e0[t] * CAPC + s0) * D + j];
        r.x = fmaf(w, v.x, r.x); r.y = fmaf(w, v.y, r.y);
        r.z = fmaf(w, v.z, r.z); r.w = fmaf(w, v.w, r.w);
    }
    int s1 = d_slot1[t];
    if (s1 >= 0) {
        float w = d_w1[t];
        const float4 v = *(const float4*)&d_eo[((size_t)d_e1[t] * CAPC + s1) * D + j];
        r.x = fmaf(w, v.x, r.x); r.y = fmaf(w, v.y, r.y);
        r.z = fmaf(w, v.z, r.z); r.w = fmaf(w, v.w, r.w);
    }
    *(float4*)&out[(size_t)t * D + j] = r;
}

// ---------------- launch ----------------
extern "C" void kernel_launch(void* const* d_in, const int* in_sizes, int n_in,
                              void* d_out, int out_size) {
    const float* x     = (const float*)d_in[0];   // [4,1024,1024]
    const float* wg    = (const float*)d_in[1];   // [1024,8]
    const float* cfc   = (const float*)d_in[2];   // [8,1024,4096]
    const float* cproj = (const float*)d_in[3];   // [8,4096,1024]
    float* out = (float*)d_out;

    float *xe, *h, *eo;
    cudaGetSymbolAddress((void**)&xe, d_xe);
    cudaGetSymbolAddress((void**)&h,  d_h);
    cudaGetSymbolAddress((void**)&eo, d_eo);

    router_kernel<<<T / 8, 256>>>(x, wg);
    rank_kernel<<<E, 1024>>>();
    gather_kernel<<<E * CAPC, 256>>>(x);

    // H = GELU(Xe @ c_fc):  [cap,1024] x [1024,4096]
    sgemm_kernel<true><<<dim3(F / 128, CAPC / 128, E), 256>>>(
        xe, cfc, h, CAPC, F, D, (size_t)CAPC * D, (size_t)D * F, (size_t)CAPC * F);

    // O = H @ c_proj: [cap,4096] x [4096,1024]
    sgemm_kernel<false><<<dim3(D / 128, CAPC / 128, E), 256>>>(
        h, cproj, eo, CAPC, D, F, (size_t)CAPC * F, (size_t)F * D, (size_t)CAPC * D);

    combine_kernel<<<T, 256>>>(out);
}

// round 16
// speedup vs baseline: 2.3554x; 2.3554x over previous
#include <cuda_runtime.h>
#include <cuda_bf16.h>
#include <math.h>
#include <stdint.h>

// ---------------- problem constants ----------------
constexpr int T    = 4096;   // tokens (B*C)
constexpr int E    = 8;      // experts
constexpr int CAPC = 1280;   // capacity per expert
constexpr int D    = 1024;   // model dim
constexpr int F    = 4096;   // hidden dim (4*d)

// ---------------- routing scratch ----------------
__device__ int   d_e0[T];
__device__ int   d_e1[T];
__device__ float d_w0[T];
__device__ float d_w1[T];
__device__ int   d_slot0[T];
__device__ int   d_slot1[T];
__device__ int   d_disp_tok[E * CAPC];
__device__ int   d_count[E];

// ---------------- split-bf16 operand buffers (zero-initialized device globals) ----------------
__device__ __nv_bfloat16 d_Ah1[(size_t)E * CAPC * D];   // dispatched tokens hi
__device__ __nv_bfloat16 d_Al1[(size_t)E * CAPC * D];   // dispatched tokens lo
__device__ __nv_bfloat16 d_B1h[(size_t)E * F * D];      // c_fc^T hi   [E][N=F][K=D]
__device__ __nv_bfloat16 d_B1l[(size_t)E * F * D];      // c_fc^T lo
__device__ __nv_bfloat16 d_Hh [(size_t)E * CAPC * F];   // gelu(H) hi  [E][cap][F]
__device__ __nv_bfloat16 d_Hl [(size_t)E * CAPC * F];   // gelu(H) lo
__device__ __nv_bfloat16 d_B2h[(size_t)E * D * F];      // c_proj^T hi [E][N=D][K=F]
__device__ __nv_bfloat16 d_B2l[(size_t)E * D * F];      // c_proj^T lo
__device__ float         d_eo [(size_t)E * CAPC * D];   // expert outputs fp32

__device__ __forceinline__ float gelu_exact(float v) {
    return 0.5f * v * (1.0f + erff(v * 0.70710678118654752f));
}

__device__ __forceinline__ uint32_t smem_to_u32(const void* p) {
    uint32_t a;
    asm("{ .reg .u64 t; cvta.to.shared.u64 t, %1; cvt.u32.u64 %0, t; }" : "=r"(a) : "l"(p));
    return a;
}

// ---------------- mma / ldmatrix / cp.async primitives (sm_80-compatible) ----------------
#define LDSM4(r0, r1, r2, r3, addr) \
    asm volatile("ldmatrix.sync.aligned.m8n8.x4.shared.b16 {%0,%1,%2,%3}, [%4];" \
        : "=r"(r0), "=r"(r1), "=r"(r2), "=r"(r3) : "r"(addr))

#define MMA16816(d, a, b0, b1) \
    asm volatile("mma.sync.aligned.m16n8k16.row.col.f32.bf16.bf16.f32 " \
        "{%0,%1,%2,%3},{%4,%5,%6,%7},{%8,%9},{%0,%1,%2,%3};" \
        : "+f"((d)[0]), "+f"((d)[1]), "+f"((d)[2]), "+f"((d)[3]) \
        : "r"((a)[0]), "r"((a)[1]), "r"((a)[2]), "r"((a)[3]), "r"(b0), "r"(b1))

#define CP_ASYNC16(dst, src) \
    asm volatile("cp.async.cg.shared.global [%0], [%1], 16;" :: "r"(dst), "l"(src))
#define CP_COMMIT() asm volatile("cp.async.commit_group;" ::: "memory")
#define CP_WAIT1()  asm volatile("cp.async.wait_group 1;" ::: "memory")
#define CP_WAIT0()  asm volatile("cp.async.wait_group 0;" ::: "memory")

// smem tile layout: 128 rows x 32 bf16 (64B) per buffer; two rows share a 128B line.
// chunk index within line (0..7, 16B units) is XORed with (line & 7) -> conflict-free ldmatrix.
__device__ __forceinline__ uint32_t sw_addr(uint32_t base, int r, int kc) {
    int line  = r >> 1;
    int chunk = ((r & 1) << 2) + kc;
    return base + (line << 7) + (((chunk ^ (line & 7))) << 4);
}

// ---------------- 1. router ----------------
__global__ void router_kernel(const float* __restrict__ x, const float* __restrict__ wg) {
    __shared__ float s_wg[E * D];
    int tid = threadIdx.x;
    for (int idx = tid; idx < E * D; idx += blockDim.x) {
        int i = idx / E, e = idx % E;
        s_wg[e * D + i] = wg[idx];
    }
    __syncthreads();
    int lane = tid & 31, wid = tid >> 5;
    int t = blockIdx.x * 8 + wid;
    const float* xr = x + (size_t)t * D;
    float acc[E];
#pragma unroll
    for (int e = 0; e < E; e++) acc[e] = 0.f;
    for (int i = lane; i < D; i += 32) {
        float xv = xr[i];
#pragma unroll
        for (int e = 0; e < E; e++) acc[e] = fmaf(xv, s_wg[e * D + i], acc[e]);
    }
#pragma unroll
    for (int e = 0; e < E; e++) {
#pragma unroll
        for (int o = 16; o > 0; o >>= 1) acc[e] += __shfl_down_sync(0xffffffffu, acc[e], o);
    }
    if (lane == 0) {
        int e0 = 0; float v0 = acc[0];
        for (int e = 1; e < E; e++) if (acc[e] > v0) { v0 = acc[e]; e0 = e; }
        int e1 = -1; float v1 = -INFINITY;
        for (int e = 0; e < E; e++) if (e != e0 && acc[e] > v1) { v1 = acc[e]; e1 = e; }
        float ex = expf(v1 - v0);
        float denom = 1.0f + ex;
        d_e0[t] = e0; d_e1[t] = e1;
        d_w0[t] = 1.0f / denom;
        d_w1[t] = ex / denom;
    }
}

// ---------------- 2. capacity rank ----------------
__global__ void rank_kernel() {
    int e = blockIdx.x;
    int tid = threadIdx.x, lane = tid & 31, wid = tid >> 5;
    __shared__ int wsum[32];
    int offset = 0;
    for (int k = 0; k < 2; k++) {
        const int* top = (k == 0) ? d_e0 : d_e1;
        int* slotArr   = (k == 0) ? d_slot0 : d_slot1;
        for (int base = 0; base < T; base += 1024) {
            int t = base + tid;
            int flag = (top[t] == e) ? 1 : 0;
            unsigned bal = __ballot_sync(0xffffffffu, flag);
            int myPre = __popc(bal & ((1u << lane) - 1u));
            if (lane == 0) wsum[wid] = __popc(bal);
            __syncthreads();
            int wbase = 0, tileTot = 0;
            for (int w = 0; w < 32; w++) { int s = wsum[w]; if (w < wid) wbase += s; tileTot += s; }
            if (flag) {
                int r = offset + wbase + myPre;
                if (r < CAPC) { slotArr[t] = r; d_disp_tok[e * CAPC + r] = t; }
                else slotArr[t] = -1;
            }
            offset += tileTot;
            __syncthreads();
        }
    }
    if (tid == 0) d_count[e] = offset < CAPC ? offset : CAPC;
}

// ---------------- 3. gather + split to bf16 hi/lo ----------------
__global__ void gather_kernel(const float* __restrict__ x) {
    int idx = blockIdx.x;                  // e*CAPC + slot
    int e = idx / CAPC, s = idx % CAPC;
    if (s >= d_count[e]) return;           // unfilled rows stay zero (zero-init globals)
    int t = d_disp_tok[idx];
    int j = threadIdx.x * 4;
    float4 v = *(const float4*)&x[(size_t)t * D + j];
    __nv_bfloat16 h0 = __float2bfloat16(v.x), h1 = __float2bfloat16(v.y);
    __nv_bfloat16 h2 = __float2bfloat16(v.z), h3 = __float2bfloat16(v.w);
    __nv_bfloat16 l0 = __float2bfloat16(v.x - __bfloat162float(h0));
    __nv_bfloat16 l1 = __float2bfloat16(v.y - __bfloat162float(h1));
    __nv_bfloat16 l2 = __float2bfloat16(v.z - __bfloat162float(h2));
    __nv_bfloat16 l3 = __float2bfloat16(v.w - __bfloat162float(h3));
    __nv_bfloat162 hp[2] = {__halves2bfloat162(h0, h1), __halves2bfloat162(h2, h3)};
    __nv_bfloat162 lp[2] = {__halves2bfloat162(l0, l1), __halves2bfloat162(l2, l3)};
    *(uint2*)&d_Ah1[(size_t)idx * D + j] = *(uint2*)hp;
    *(uint2*)&d_Al1[(size_t)idx * D + j] = *(uint2*)lp;
}

// ---------------- 4. weight transpose + split:  W[e][K][N] -> hiT/loT [e][N][K] ----------------
__global__ void transpose_split_kernel(const float* __restrict__ W,
                                       __nv_bfloat16* __restrict__ hiT,
                                       __nv_bfloat16* __restrict__ loT,
                                       int K, int N) {
    __shared__ float tile[32][33];
    int e = blockIdx.z;
    const float* We = W + (size_t)e * K * N;
    size_t obase = (size_t)e * K * N;
    int nb = blockIdx.x * 32, kb = blockIdx.y * 32;
    int tx = threadIdx.x, ty = threadIdx.y;
#pragma unroll
    for (int r = 0; r < 32; r += 8)
        tile[ty + r][tx] = We[(size_t)(kb + ty + r) * N + nb + tx];
    __syncthreads();
#pragma unroll
    for (int r = 0; r < 32; r += 8) {
        float v = tile[tx][ty + r];
        __nv_bfloat16 h = __float2bfloat16(v);
        __nv_bfloat16 l = __float2bfloat16(v - __bfloat162float(h));
        size_t o = obase + (size_t)(nb + ty + r) * K + kb + tx;
        hiT[o] = h; loT[o] = l;
    }
}

// ---------------- 5. split-bf16 HMMA GEMM (mma.sync m16n8k16) ----------------
// CTA tile 128(M) x 128(N), BK=32 bf16, 256 threads = 8 warps (2 M x 4 N), warp tile 64x32.
// Double-buffered cp.async pipeline. 3 mma terms: Ah*Bh + Ah*Bl + Al*Bh.
constexpr int S_AH = 0;
constexpr int S_AL = 8 * 1024;
constexpr int S_BH = 16 * 1024;
constexpr int S_BL = 24 * 1024;
constexpr int STAGE_BYTES = 32 * 1024;
constexpr int SMEM_GEMM = 2 * STAGE_BYTES;

template <bool GELU_SPLIT>
__global__ __launch_bounds__(256) void mma_gemm_kernel(
    const __nv_bfloat16* __restrict__ Ah, const __nv_bfloat16* __restrict__ Al,
    const __nv_bfloat16* __restrict__ Bh, const __nv_bfloat16* __restrict__ Bl,
    __nv_bfloat16* __restrict__ OutH, __nv_bfloat16* __restrict__ OutL,
    float* __restrict__ OutF, int K, int Ntot)
{
    extern __shared__ char smem[];
    const uint32_t sb = smem_to_u32(smem);
    const int tid = threadIdx.x, lane = tid & 31, w = tid >> 5;
    const int e  = blockIdx.z;
    const int m0 = blockIdx.y * 128;
    const int n0 = blockIdx.x * 128;

    Ah += (size_t)e * CAPC * K + (size_t)m0 * K;
    Al += (size_t)e * CAPC * K + (size_t)m0 * K;
    Bh += (size_t)e * Ntot * K + (size_t)n0 * K;
    Bl += (size_t)e * Ntot * K + (size_t)n0 * K;

    // loader mapping: each thread owns row r, two 16B chunks kc0,kc0+1 in each buffer
    const int lr  = tid >> 1;
    const int kc0 = (tid & 1) * 2;

    auto load_stage = [&](int st, int k0) {
        uint32_t s0 = sb + st * STAGE_BYTES;
        const __nv_bfloat16* gA_h = Ah + (size_t)lr * K + k0 + kc0 * 8;
        const __nv_bfloat16* gA_l = Al + (size_t)lr * K + k0 + kc0 * 8;
        const __nv_bfloat16* gB_h = Bh + (size_t)lr * K + k0 + kc0 * 8;
        const __nv_bfloat16* gB_l = Bl + (size_t)lr * K + k0 + kc0 * 8;
#pragma unroll
        for (int c = 0; c < 2; c++) {
            uint32_t a0 = sw_addr(s0 + S_AH, lr, kc0 + c);
            uint32_t a1 = sw_addr(s0 + S_AL, lr, kc0 + c);
            uint32_t a2 = sw_addr(s0 + S_BH, lr, kc0 + c);
            uint32_t a3 = sw_addr(s0 + S_BL, lr, kc0 + c);
            CP_ASYNC16(a0, gA_h + c * 8);
            CP_ASYNC16(a1, gA_l + c * 8);
            CP_ASYNC16(a2, gB_h + c * 8);
            CP_ASYNC16(a3, gB_l + c * 8);
        }
    };

    // warp tile position
    const int wm = (w & 1) * 64;        // 2 warps over M (64 rows each)
    const int wn = (w >> 1) * 32;       // 4 warps over N (32 cols each)
    // ldmatrix lane row/chunk components
    const int a_lr = (lane & 7) + ((lane >> 3) & 1) * 8;  // A: row within 16-row tile
    const int a_lc = lane >> 4;                           // A: chunk offset 0/1
    const int b_lr = (lane & 7) + (lane >> 4) * 8;        // B: row within 16-row tile
    const int b_lc = (lane >> 3) & 1;                     // B: chunk offset 0/1

    float acc[4][4][4];
#pragma unroll
    for (int i = 0; i < 4; i++)
#pragma unroll
        for (int j = 0; j < 4; j++)
#pragma unroll
            for (int q = 0; q < 4; q++) acc[i][j][q] = 0.f;

    const int NS = K / 32;
    load_stage(0, 0);
    CP_COMMIT();

    for (int s = 0; s < NS; s++) {
        const int cur = s & 1;
        if (s + 1 < NS) {
            load_stage(cur ^ 1, (s + 1) * 32);
            CP_COMMIT();
            CP_WAIT1();
        } else {
            CP_WAIT0();
        }
        __syncthreads();

        const uint32_t st = sb + cur * STAGE_BYTES;
#pragma unroll
        for (int kk = 0; kk < 2; kk++) {           // two k16 steps
            const int ct = kk * 2;                 // 16B-chunk base of this k16
            uint32_t ah[4][4], al[4][4], bh[2][4], bl[2][4];
#pragma unroll
            for (int mi = 0; mi < 4; mi++) {
                int r = wm + mi * 16 + a_lr;
                LDSM4(ah[mi][0], ah[mi][1], ah[mi][2], ah[mi][3], sw_addr(st + S_AH, r, ct + a_lc));
                LDSM4(al[mi][0], al[mi][1], al[mi][2], al[mi][3], sw_addr(st + S_AL, r, ct + a_lc));
            }
#pragma unroll
            for (int nt = 0; nt < 2; nt++) {
                int r = wn + nt * 16 + b_lr;
                LDSM4(bh[nt][0], bh[nt][1], bh[nt][2], bh[nt][3], sw_addr(st + S_BH, r, ct + b_lc));
                LDSM4(bl[nt][0], bl[nt][1], bl[nt][2], bl[nt][3], sw_addr(st + S_BL, r, ct + b_lc));
            }
#pragma unroll
            for (int mi = 0; mi < 4; mi++) {
#pragma unroll
                for (int ni = 0; ni < 4; ni++) {
                    const int nt = ni >> 1, o = (ni & 1) * 2;
                    MMA16816(acc[mi][ni], ah[mi], bh[nt][o], bh[nt][o + 1]);
                    MMA16816(acc[mi][ni], ah[mi], bl[nt][o], bl[nt][o + 1]);
                    MMA16816(acc[mi][ni], al[mi], bh[nt][o], bh[nt][o + 1]);
                }
            }
        }
        __syncthreads();
    }

    // ---------------- epilogue ----------------
    const int er = lane >> 2;            // row within m16 tile
    const int ec = (lane & 3) * 2;       // col pair within n8 tile
#pragma unroll
    for (int mi = 0; mi < 4; mi++) {
#pragma unroll
        for (int ni = 0; ni < 4; ni++) {
            int row0 = m0 + wm + mi * 16 + er;
            int col  = n0 + wn + ni * 8 + ec;
#pragma unroll
            for (int h = 0; h < 2; h++) {          // the two 8-row halves
                int row = row0 + h * 8;
                float v0 = acc[mi][ni][h * 2 + 0];
                float v1 = acc[mi][ni][h * 2 + 1];
                size_t o = ((size_t)e * CAPC + row) * Ntot + col;
                if (GELU_SPLIT) {
                    v0 = gelu_exact(v0); v1 = gelu_exact(v1);
                    __nv_bfloat16 h0 = __float2bfloat16(v0);
                    __nv_bfloat16 h1 = __float2bfloat16(v1);
                    __nv_bfloat16 l0 = __float2bfloat16(v0 - __bfloat162float(h0));
                    __nv_bfloat16 l1 = __float2bfloat16(v1 - __bfloat162float(h1));
                    *(__nv_bfloat162*)(OutH + o) = __halves2bfloat162(h0, h1);
                    *(__nv_bfloat162*)(OutL + o) = __halves2bfloat162(l0, l1);
                } else {
                    *(float2*)(OutF + o) = make_float2(v0, v1);
                }
            }
        }
    }
}

// ---------------- 6. weighted combine ----------------
__global__ void combine_kernel(float* __restrict__ out) {
    int t = blockIdx.x;
    int j = threadIdx.x * 4;
    float4 r = {0.f, 0.f, 0.f, 0.f};
    int s0 = d_slot0[t];
    if (s0 >= 0) {
        float w = d_w0[t];
        const float4 v = *(const float4*)&d_eo[((size_t)d_e0[t] * CAPC + s0) * D + j];
        r.x = fmaf(w, v.x, r.x); r.y = fmaf(w, v.y, r.y);
        r.z = fmaf(w, v.z, r.z); r.w = fmaf(w, v.w, r.w);
    }
    int s1 = d_slot1[t];
    if (s1 >= 0) {
        float w = d_w1[t];
        const float4 v = *(const float4*)&d_eo[((size_t)d_e1[t] * CAPC + s1) * D + j];
        r.x = fmaf(w, v.x, r.x); r.y = fmaf(w, v.y, r.y);
        r.z = fmaf(w, v.z, r.z); r.w = fmaf(w, v.w, r.w);
    }
    *(float4*)&out[(size_t)t * D + j] = r;
}

// ---------------- launch ----------------
extern "C" void kernel_launch(void* const* d_in, const int* in_sizes, int n_in,
                              void* d_out, int out_size) {
    const float* x     = (const float*)d_in[0];   // [4,1024,1024]
    const float* wg    = (const float*)d_in[1];   // [1024,8]
    const float* cfc   = (const float*)d_in[2];   // [8,1024,4096]
    const float* cproj = (const float*)d_in[3];   // [8,4096,1024]
    float* out = (float*)d_out;

    __nv_bfloat16 *Ah1, *Al1, *B1h, *B1l, *Hh, *Hl, *B2h, *B2l;
    float* eo;
    cudaGetSymbolAddress((void**)&Ah1, d_Ah1);
    cudaGetSymbolAddress((void**)&Al1, d_Al1);
    cudaGetSymbolAddress((void**)&B1h, d_B1h);
    cudaGetSymbolAddress((void**)&B1l, d_B1l);
    cudaGetSymbolAddress((void**)&Hh,  d_Hh);
    cudaGetSymbolAddress((void**)&Hl,  d_Hl);
    cudaGetSymbolAddress((void**)&B2h, d_B2h);
    cudaGetSymbolAddress((void**)&B2l, d_B2l);
    cudaGetSymbolAddress((void**)&eo,  d_eo);

    cudaFuncSetAttribute(mma_gemm_kernel<true>,  cudaFuncAttributeMaxDynamicSharedMemorySize, SMEM_GEMM);
    cudaFuncSetAttribute(mma_gemm_kernel<false>, cudaFuncAttributeMaxDynamicSharedMemorySize, SMEM_GEMM);

    // weight transpose + split (independent of routing)
    transpose_split_kernel<<<dim3(F / 32, D / 32, E), dim3(32, 8)>>>(cfc,   B1h, B1l, D, F);
    transpose_split_kernel<<<dim3(D / 32, F / 32, E), dim3(32, 8)>>>(cproj, B2h, B2l, F, D);

    router_kernel<<<T / 8, 256>>>(x, wg);
    rank_kernel<<<E, 1024>>>();
    gather_kernel<<<E * CAPC, 256>>>(x);

    // GEMM1: H = gelu(Xe @ c_fc) -> split-bf16 Hh/Hl   [1280,1024]x[1024,4096] per expert
    mma_gemm_kernel<true><<<dim3(F / 128, CAPC / 128, E), 256, SMEM_GEMM>>>(
        Ah1, Al1, B1h, B1l, Hh, Hl, nullptr, D, F);

    // GEMM2: O = H @ c_proj -> fp32 eo   [1280,4096]x[4096,1024] per expert
    mma_gemm_kernel<false><<<dim3(D / 128, CAPC / 128, E), 256, SMEM_GEMM>>>(
        Hh, Hl, B2h, B2l, nullptr, nullptr, eo, F, D);

    combine_kernel<<<T, 256>>>(out);
}